// round 3
// baseline (speedup 1.0000x reference)
#include <cuda_runtime.h>

#define N_NODES 25000
#define N_EDGES 320000
#define F       64
#define NHEADS  5
#define NRELS   20
#define NBASES  10
#define OUTC    320
#define PCOLS   200          // composed attention-projection weight cols (100 s + 100 d)
#define TOTC    584          // 64 (z) + 320 (self_z) + 200 (Ps|Pd)
#define PSTRIDE 160          // per-node padded P row: 20 rels * 8 slots

// ---------------- static device scratch ------------------------------------
__device__ float    g_z [N_NODES * F];            // 6.4 MB
__device__ float    g_W2[64 * PCOLS];             // composed weights fc_w@afc
__device__ float    g_Ps[N_NODES * PSTRIDE];      // 16 MB  Ps[n][r][h] (pad 8)
__device__ float    g_Pd[N_NODES * PSTRIDE];      // 16 MB
__device__ int      g_cnt [N_NODES];
__device__ int      g_scan[N_NODES];
__device__ int      g_bsum[32];
__device__ int      g_bpre[32];
__device__ int      g_off [N_NODES + 1];
__device__ int      g_cur [N_NODES];
__device__ unsigned g_srcrt[N_EDGES];             // src | (rel<<16), sorted by dst

// ---------------- f32x2 packed helpers -------------------------------------
__device__ __forceinline__ unsigned long long pack2(float x) {
    unsigned long long r;
    asm("mov.b64 %0, {%1, %1};" : "=l"(r) : "f"(x));
    return r;
}
__device__ __forceinline__ void fma2(unsigned long long& d,
                                     unsigned long long a, unsigned long long b) {
    asm("fma.rn.f32x2 %0, %1, %2, %0;" : "+l"(d) : "l"(a), "l"(b));
}
__device__ __forceinline__ void unpack2(unsigned long long v, float& lo, float& hi) {
    asm("mov.b64 {%0, %1}, %2;" : "=f"(lo), "=f"(hi) : "l"(v));
}

// ---------------------------------------------------------------------------
// Kernel 1: compose W2[k][c] = sum_f fc_w[k][f] * afc[r][f(+64)][h]
// where afc[r][f][h] = sum_b w_comp[r][b] * aw[b][f][h].  One block per r.
// Col c: 0..99 = s-part (r*5+h), 100..199 = d-part.
// ---------------------------------------------------------------------------
__global__ void __launch_bounds__(320) attn_comp2_kernel(const float* __restrict__ aw,
                                                         const float* __restrict__ w_comp,
                                                         const float* __restrict__ fc_w)
{
    __shared__ float afc[128 * NHEADS];          // [f][h]
    const int r = blockIdx.x, tid = threadIdx.x;

    if (tid < 128) {
        float acc[NHEADS] = {};
#pragma unroll
        for (int b = 0; b < NBASES; b++) {
            float wc = w_comp[r * NBASES + b];
#pragma unroll
            for (int h = 0; h < NHEADS; h++)
                acc[h] += wc * aw[(b * 128 + tid) * NHEADS + h];
        }
#pragma unroll
        for (int h = 0; h < NHEADS; h++) afc[tid * NHEADS + h] = acc[h];
    }
    __syncthreads();

    for (int o = tid; o < 640; o += 320) {
        int k  = o / 10;
        int c2 = o % 10;
        int h  = c2 % 5;
        const float* af = afc + (c2 >= 5 ? 64 * NHEADS : 0) + h;
        float sum = 0.f;
#pragma unroll
        for (int f = 0; f < 64; f++) sum += fc_w[k * 64 + f] * af[f * NHEADS];
        int col = (c2 >= 5 ? 100 : 0) + r * 5 + h;
        g_W2[k * PCOLS + col] = sum;
    }
}

// ---------------------------------------------------------------------------
// Kernel 2: fused projection GEMM with packed f32x2 FMA.
// feat[25000x64] @ [fc_w | self_fc_w | W2] -> cols 0..63 g_z, 64..383 d_out,
// 384..583 g_Ps/g_Pd (padded layout).  Tile 64x128, 256 thr, 4x8 microtile.
// ---------------------------------------------------------------------------
__global__ void __launch_bounds__(256) proj_kernel(const float* __restrict__ feat,
                                                   const float* __restrict__ fc_w,
                                                   const float* __restrict__ self_fc_w,
                                                   float* __restrict__ out)
{
    __shared__ float As[64][64];    // 16 KB
    __shared__ float Bs[64][128];   // 32 KB  (total 48 KB static)

    const int tid = threadIdx.x;
    const int m0  = blockIdx.x * 64;
    const int c0  = blockIdx.y * 128;

    // A tile: 64 rows x 16 float4
#pragma unroll
    for (int i = 0; i < 4; i++) {
        int v = tid + i * 256;
        int row = v >> 4, k4 = (v & 15) * 4;
        int node = m0 + row;
        float4 a = make_float4(0.f, 0.f, 0.f, 0.f);
        if (node < N_NODES) a = *(const float4*)(feat + node * F + k4);
        As[row][k4 + 0] = a.x; As[row][k4 + 1] = a.y;
        As[row][k4 + 2] = a.z; As[row][k4 + 3] = a.w;
    }
    // B tile: 64 k-rows x 32 float4
#pragma unroll
    for (int i = 0; i < 8; i++) {
        int v = tid + i * 256;
        int k = v >> 5, c4 = (v & 31) * 4;
        int gc = c0 + c4;
        float4 b = make_float4(0.f, 0.f, 0.f, 0.f);
        if (gc < 64)        b = *(const float4*)(fc_w + k * 64 + gc);
        else if (gc < 384)  b = *(const float4*)(self_fc_w + k * 320 + (gc - 64));
        else if (gc < TOTC) b = *(const float4*)(g_W2 + k * PCOLS + (gc - 384));
        *(float4*)&Bs[k][c4] = b;
    }
    __syncthreads();

    const int tx = tid & 15, ty = tid >> 4;     // cols 8*tx.., rows 4*ty..
    unsigned long long acc[4][4];
#pragma unroll
    for (int i = 0; i < 4; i++)
#pragma unroll
        for (int j = 0; j < 4; j++) acc[i][j] = 0ull;

#pragma unroll
    for (int k = 0; k < 64; k++) {
        unsigned long long a2[4], b2[4];
#pragma unroll
        for (int i = 0; i < 4; i++) a2[i] = pack2(As[4 * ty + i][k]);
        const unsigned long long* bp = (const unsigned long long*)&Bs[k][8 * tx];
#pragma unroll
        for (int j = 0; j < 4; j++) b2[j] = bp[j];
#pragma unroll
        for (int i = 0; i < 4; i++)
#pragma unroll
            for (int j = 0; j < 4; j++) fma2(acc[i][j], a2[i], b2[j]);
    }

#pragma unroll
    for (int i = 0; i < 4; i++) {
        int node = m0 + 4 * ty + i;
        if (node >= N_NODES) continue;
#pragma unroll
        for (int j = 0; j < 4; j++) {
            int gc = c0 + 8 * tx + 2 * j;
            if (gc < 64) {
                *(unsigned long long*)(g_z + node * F + gc) = acc[i][j];
            } else if (gc < 384) {
                *(unsigned long long*)(out + node * OUTC + (gc - 64)) = acc[i][j];
            } else if (gc < TOTC) {
                float lo, hi;
                unpack2(acc[i][j], lo, hi);
                int idx = gc - 384;
#pragma unroll
                for (int t = 0; t < 2; t++) {
                    float vf = t ? hi : lo;
                    int ix = idx + t;
                    if (ix < 100) g_Ps[node * PSTRIDE + (ix / 5) * 8 + (ix % 5)] = vf;
                    else { int jx = ix - 100;
                           g_Pd[node * PSTRIDE + (jx / 5) * 8 + (jx % 5)] = vf; }
                }
            }
        }
    }
}

// ---------------------------------------------------------------------------
// Counting sort by dst: zero -> hist(int4) -> 3-kernel scan -> scatter(int4)
// ---------------------------------------------------------------------------
__global__ void zero_cnt_kernel()
{
    int i = blockIdx.x * blockDim.x + threadIdx.x;
    if (i < N_NODES) g_cnt[i] = 0;
}

__global__ void hist_kernel(const int* __restrict__ dst)
{
    int t = blockIdx.x * blockDim.x + threadIdx.x;
    if (t < N_EDGES / 4) {
        int4 d = ((const int4*)dst)[t];
        atomicAdd(&g_cnt[d.x], 1); atomicAdd(&g_cnt[d.y], 1);
        atomicAdd(&g_cnt[d.z], 1); atomicAdd(&g_cnt[d.w], 1);
    }
}

__global__ void __launch_bounds__(1024) scan1_kernel()
{
    __shared__ int wsum[32];
    const int tid = threadIdx.x, lane = tid & 31, wid = tid >> 5;
    const int idx = blockIdx.x * 1024 + tid;
    int v = (idx < N_NODES) ? g_cnt[idx] : 0;
    int x = v;
#pragma unroll
    for (int d = 1; d < 32; d <<= 1) {
        int y = __shfl_up_sync(0xffffffffu, x, d);
        if (lane >= d) x += y;
    }
    if (lane == 31) wsum[wid] = x;
    __syncthreads();
    if (tid < 32) {
        int w = wsum[tid];
#pragma unroll
        for (int d = 1; d < 32; d <<= 1) {
            int y = __shfl_up_sync(0xffffffffu, w, d);
            if (tid >= d) w += y;
        }
        wsum[tid] = w;
    }
    __syncthreads();
    int incl = x + (wid > 0 ? wsum[wid - 1] : 0);
    if (idx < N_NODES) g_scan[idx] = incl;
    if (tid == 1023)   g_bsum[blockIdx.x] = incl;
}

__global__ void scan2_kernel(int nblocks)
{
    int t = threadIdx.x;
    int v = (t < nblocks) ? g_bsum[t] : 0;
    int x = v;
#pragma unroll
    for (int d = 1; d < 32; d <<= 1) {
        int y = __shfl_up_sync(0xffffffffu, x, d);
        if (t >= d) x += y;
    }
    if (t < nblocks) g_bpre[t] = x - v;
}

__global__ void __launch_bounds__(1024) scan3_kernel()
{
    int idx = blockIdx.x * 1024 + threadIdx.x;
    if (idx < N_NODES) {
        int off = g_scan[idx] + g_bpre[blockIdx.x];
        g_off[idx + 1] = off;
        g_cur[idx]     = off - g_cnt[idx];
    }
    if (idx == 0) g_off[0] = 0;
}

__global__ void scatter_kernel(const int* __restrict__ dst,
                               const int* __restrict__ src,
                               const int* __restrict__ et)
{
    int t = blockIdx.x * blockDim.x + threadIdx.x;
    if (t >= N_EDGES / 4) return;
    int4 d = ((const int4*)dst)[t];
    int4 s = ((const int4*)src)[t];
    int4 r = ((const int4*)et)[t];
    int dd[4] = {d.x, d.y, d.z, d.w};
    int ss[4] = {s.x, s.y, s.z, s.w};
    int rr[4] = {r.x, r.y, r.z, r.w};
#pragma unroll
    for (int j = 0; j < 4; j++) {
        int pos = atomicAdd(&g_cur[dd[j]], 1);
        g_srcrt[pos] = (unsigned)ss[j] | ((unsigned)rr[j] << 16);
    }
}

// ---------------------------------------------------------------------------
// Kernel 3: warp-per-dst gather. Shuffle-free: att = leaky(Ps[s,r]+Pd[n,r]).
// ---------------------------------------------------------------------------
#define GB 512

__global__ void __launch_bounds__(256) gather_kernel(float* __restrict__ out)
{
    const int w = threadIdx.x >> 5, lane = threadIdx.x & 31;

    for (int n = blockIdx.x * 8 + w; n < N_NODES; n += GB * 8) {
        const int beg = g_off[n], end = g_off[n + 1];
        if (beg >= end) continue;

        const float* pdb = g_Pd + n * PSTRIDE;
        float acc[2 * NHEADS];
#pragma unroll
        for (int q = 0; q < 2 * NHEADS; q++) acc[q] = 0.f;

        // prefetch edge `beg`
        unsigned pk = g_srcrt[beg];
        int s = pk & 0xFFFFu, r = pk >> 16;
        float2 zs = *(const float2*)(g_z + s * F + 2 * lane);
        const float* pp = g_Ps + s * PSTRIDE + r * 8;
        float4 ps4 = *(const float4*)pp;  float ps1 = pp[4];
        const float* qq = pdb + r * 8;
        float4 pd4 = *(const float4*)qq;  float pd1 = qq[4];

        for (int i = beg; i < end; i++) {
            const float2 czs = zs;
            const float4 cps4 = ps4, cpd4 = pd4;
            const float  cps1 = ps1, cpd1 = pd1;
            if (i + 1 < end) {
                unsigned pk2_ = g_srcrt[i + 1];
                int s2 = pk2_ & 0xFFFFu, r2 = pk2_ >> 16;
                zs = *(const float2*)(g_z + s2 * F + 2 * lane);
                const float* p2 = g_Ps + s2 * PSTRIDE + r2 * 8;
                ps4 = *(const float4*)p2;  ps1 = p2[4];
                const float* p3 = pdb + r2 * 8;
                pd4 = *(const float4*)p3;  pd1 = p3[4];
            }
            float a0 = cps4.x + cpd4.x;
            float a1 = cps4.y + cpd4.y;
            float a2 = cps4.z + cpd4.z;
            float a3 = cps4.w + cpd4.w;
            float a4 = cps1   + cpd1;
            a0 = a0 > 0.f ? a0 : 0.01f * a0;
            a1 = a1 > 0.f ? a1 : 0.01f * a1;
            a2 = a2 > 0.f ? a2 : 0.01f * a2;
            a3 = a3 > 0.f ? a3 : 0.01f * a3;
            a4 = a4 > 0.f ? a4 : 0.01f * a4;
            acc[0] += a0 * czs.x;  acc[1] += a0 * czs.y;
            acc[2] += a1 * czs.x;  acc[3] += a1 * czs.y;
            acc[4] += a2 * czs.x;  acc[5] += a2 * czs.y;
            acc[6] += a3 * czs.x;  acc[7] += a3 * czs.y;
            acc[8] += a4 * czs.x;  acc[9] += a4 * czs.y;
        }

        float* ob = out + (long)n * OUTC + 2 * lane;
#pragma unroll
        for (int h = 0; h < NHEADS; h++) {
            float2 o = *(float2*)(ob + h * F);
            o.x += acc[2 * h];
            o.y += acc[2 * h + 1];
            *(float2*)(ob + h * F) = o;
        }
    }
}

// ---------------------------------------------------------------------------
extern "C" void kernel_launch(void* const* d_in, const int* in_sizes, int n_in,
                              void* d_out, int out_size)
{
    const float* feat      = (const float*)d_in[0];
    const int*   src       = (const int*)  d_in[1];
    const int*   dst       = (const int*)  d_in[2];
    const int*   etype     = (const int*)  d_in[3];
    const float* fc_w      = (const float*)d_in[4];
    const float* self_fc_w = (const float*)d_in[5];
    const float* aw        = (const float*)d_in[6];
    const float* w_comp    = (const float*)d_in[7];
    float* out = (float*)d_out;

    const int NB = (N_NODES + 1023) / 1024;         // 25

    attn_comp2_kernel<<<NRELS, 320>>>(aw, w_comp, fc_w);
    proj_kernel<<<dim3((N_NODES + 63) / 64, 5), 256>>>(feat, fc_w, self_fc_w, out);

    zero_cnt_kernel<<<(N_NODES + 255) / 256, 256>>>();
    hist_kernel<<<(N_EDGES / 4 + 255) / 256, 256>>>(dst);
    scan1_kernel<<<NB, 1024>>>();
    scan2_kernel<<<1, 32>>>(NB);
    scan3_kernel<<<NB, 1024>>>();
    scatter_kernel<<<(N_EDGES / 4 + 255) / 256, 256>>>(dst, src, etype);

    gather_kernel<<<GB, 256>>>(out);
}

// round 4
// speedup vs baseline: 2.1204x; 2.1204x over previous
#include <cuda_runtime.h>

#define N_NODES 25000
#define N_EDGES 320000
#define F       64
#define NHEADS  5
#define NRELS   20
#define NBASES  10
#define OUTC    320
#define PCOLS   200          // 100 s-cols + 100 d-cols
#define TOTC    584          // 64 z + 320 self_z + 200 P
#define CHUNK   32           // edges per warp in gather

// ---------------- static device scratch ------------------------------------
__device__ float    g_z [N_NODES * F];        // 6.4 MB
__device__ float    g_W2[64 * PCOLS];
__device__ float    g_P [N_NODES * PCOLS];    // 20 MB: [n][0..99]=Ps, [100..199]=Pd
__device__ int      g_cnt [N_NODES];
__device__ int      g_scan[N_NODES];
__device__ int      g_bsum[32];
__device__ int      g_cur [N_NODES];
__device__ unsigned g_srcrt[N_EDGES];         // src | rel<<16, sorted by dst
__device__ int      g_dstS [N_EDGES];         // dst, sorted

// ---------------- f32x2 helpers ---------------------------------------------
__device__ __forceinline__ unsigned long long pack2(float x) {
    unsigned long long r; asm("mov.b64 %0, {%1, %1};" : "=l"(r) : "f"(x)); return r;
}
__device__ __forceinline__ void fma2(unsigned long long& d,
                                     unsigned long long a, unsigned long long b) {
    asm("fma.rn.f32x2 %0, %1, %2, %0;" : "+l"(d) : "l"(a), "l"(b));
}

// ---------------------------------------------------------------------------
// K1: attention-weight composition (+ zero g_cnt).  One block per relation.
// W2[k][r*5+h]     = sum_f fc_w[k][f] * afc[r][f][h]
// W2[k][100+r*5+h] = sum_f fc_w[k][f] * afc[r][64+f][h]
// ---------------------------------------------------------------------------
__global__ void __launch_bounds__(320) attn_zero_kernel(const float* __restrict__ aw,
                                                        const float* __restrict__ w_comp,
                                                        const float* __restrict__ fc_w)
{
    __shared__ float afc[128 * NHEADS];
    const int r = blockIdx.x, tid = threadIdx.x;

    for (int i = r * 320 + tid; i < N_NODES; i += NRELS * 320) g_cnt[i] = 0;

    if (tid < 128) {
        float acc[NHEADS] = {};
#pragma unroll
        for (int b = 0; b < NBASES; b++) {
            float wc = w_comp[r * NBASES + b];
#pragma unroll
            for (int h = 0; h < NHEADS; h++)
                acc[h] += wc * aw[(b * 128 + tid) * NHEADS + h];
        }
#pragma unroll
        for (int h = 0; h < NHEADS; h++) afc[tid * NHEADS + h] = acc[h];
    }
    __syncthreads();

    for (int o = tid; o < 640; o += 320) {
        int k = o / 10, c2 = o % 10, h = c2 % 5;
        const float* af = afc + (c2 >= 5 ? 64 * NHEADS : 0) + h;
        float sum = 0.f;
#pragma unroll
        for (int f = 0; f < 64; f++) sum += fc_w[k * 64 + f] * af[f * NHEADS];
        g_W2[k * PCOLS + (c2 >= 5 ? 100 : 0) + r * 5 + h] = sum;
    }
}

// ---------------------------------------------------------------------------
// Sort by dst: hist -> scan1 -> scan3 -> scatter
// ---------------------------------------------------------------------------
__global__ void hist_kernel(const int* __restrict__ dst)
{
    int e = blockIdx.x * blockDim.x + threadIdx.x;
    if (e < N_EDGES) atomicAdd(&g_cnt[dst[e]], 1);
}

__global__ void __launch_bounds__(1024) scan1_kernel()
{
    __shared__ int wsum[32];
    const int tid = threadIdx.x, lane = tid & 31, wid = tid >> 5;
    const int idx = blockIdx.x * 1024 + tid;
    int v = (idx < N_NODES) ? g_cnt[idx] : 0;
    int x = v;
#pragma unroll
    for (int d = 1; d < 32; d <<= 1) {
        int y = __shfl_up_sync(0xffffffffu, x, d);
        if (lane >= d) x += y;
    }
    if (lane == 31) wsum[wid] = x;
    __syncthreads();
    if (tid < 32) {
        int w = wsum[tid];
#pragma unroll
        for (int d = 1; d < 32; d <<= 1) {
            int y = __shfl_up_sync(0xffffffffu, w, d);
            if (tid >= d) w += y;
        }
        wsum[tid] = w;
    }
    __syncthreads();
    int incl = x + (wid > 0 ? wsum[wid - 1] : 0);
    if (idx < N_NODES) g_scan[idx] = incl;
    if (tid == 1023)   g_bsum[blockIdx.x] = incl;
}

__global__ void __launch_bounds__(1024) scan3_kernel()
{
    int idx = blockIdx.x * 1024 + threadIdx.x;
    int pre = 0;
    for (int b = 0; b < blockIdx.x; b++) pre += g_bsum[b];
    if (idx < N_NODES) {
        int off = g_scan[idx] + pre;
        g_cur[idx] = off - g_cnt[idx];   // exclusive start = scatter cursor
    }
}

__global__ void scatter_kernel(const int* __restrict__ dst,
                               const int* __restrict__ src,
                               const int* __restrict__ et)
{
    int e = blockIdx.x * blockDim.x + threadIdx.x;
    if (e < N_EDGES) {
        int d = dst[e];
        int pos = atomicAdd(&g_cur[d], 1);
        g_srcrt[pos] = (unsigned)src[e] | ((unsigned)et[e] << 16);
        g_dstS[pos]  = d;
    }
}

// ---------------------------------------------------------------------------
// K6 (profiled): fused projection GEMM, f32x2.
// feat @ [fc_w | self_fc_w | W2]: cols 0..63 -> g_z, 64..383 -> d_out,
// 384..583 -> g_P.  128x128 tile, 256 thr, 8x8 microtile.
// ---------------------------------------------------------------------------
__global__ void __launch_bounds__(256) proj_kernel(const float* __restrict__ feat,
                                                   const float* __restrict__ fc_w,
                                                   const float* __restrict__ self_fc_w,
                                                   float* __restrict__ out)
{
    __shared__ float As[128][65];
    __shared__ float Bs[64][132];

    const int tid = threadIdx.x;
    const int m0  = blockIdx.x * 128;
    const int c0  = blockIdx.y * 128;

#pragma unroll
    for (int i = 0; i < 8; i++) {
        int v = tid + i * 256;
        int row = v >> 4, k4 = (v & 15) * 4;
        int node = m0 + row;
        float4 a = make_float4(0.f, 0.f, 0.f, 0.f);
        if (node < N_NODES) a = *(const float4*)(feat + node * F + k4);
        As[row][k4 + 0] = a.x; As[row][k4 + 1] = a.y;
        As[row][k4 + 2] = a.z; As[row][k4 + 3] = a.w;
    }
#pragma unroll
    for (int i = 0; i < 8; i++) {
        int v = tid + i * 256;
        int k = v >> 5, c4 = (v & 31) * 4;
        int gc = c0 + c4;
        float4 b = make_float4(0.f, 0.f, 0.f, 0.f);
        if (gc < 64)        b = *(const float4*)(fc_w + k * 64 + gc);
        else if (gc < 384)  b = *(const float4*)(self_fc_w + k * 320 + (gc - 64));
        else if (gc < TOTC) b = *(const float4*)(g_W2 + k * PCOLS + (gc - 384));
        *(float4*)&Bs[k][c4] = b;
    }
    __syncthreads();

    const int tx = tid & 15, ty = tid >> 4;
    unsigned long long acc[8][4];
#pragma unroll
    for (int i = 0; i < 8; i++)
#pragma unroll
        for (int j = 0; j < 4; j++) acc[i][j] = 0ull;

#pragma unroll 16
    for (int k = 0; k < 64; k++) {
        unsigned long long a2[8], b2[4];
#pragma unroll
        for (int i = 0; i < 8; i++) a2[i] = pack2(As[8 * ty + i][k]);
        const unsigned long long* bp = (const unsigned long long*)&Bs[k][8 * tx];
#pragma unroll
        for (int j = 0; j < 4; j++) b2[j] = bp[j];
#pragma unroll
        for (int i = 0; i < 8; i++)
#pragma unroll
            for (int j = 0; j < 4; j++) fma2(acc[i][j], a2[i], b2[j]);
    }

#pragma unroll
    for (int i = 0; i < 8; i++) {
        int node = m0 + 8 * ty + i;
        if (node >= N_NODES) continue;
#pragma unroll
        for (int j = 0; j < 4; j++) {
            int gc = c0 + 8 * tx + 2 * j;
            if (gc < 64)
                *(unsigned long long*)(g_z + node * F + gc) = acc[i][j];
            else if (gc < 384)
                *(unsigned long long*)(out + node * OUTC + (gc - 64)) = acc[i][j];
            else if (gc < TOTC)
                *(unsigned long long*)(g_P + node * PCOLS + (gc - 384)) = acc[i][j];
        }
    }
}

// ---------------------------------------------------------------------------
// K7: edge-parallel aggregating gather. Warp owns CHUNK sorted edges;
// register-accumulates per dst-run; flushes via smem-staged red.v4.
// ---------------------------------------------------------------------------
__global__ void __launch_bounds__(256) gather_kernel(float* __restrict__ out)
{
    __shared__ float stage[8][328];
    const int w = threadIdx.x >> 5, lane = threadIdx.x & 31;
    const int gw = blockIdx.x * 8 + w;
    const int e0 = gw * CHUNK;
    if (e0 >= N_EDGES) return;
    const int e1 = min(e0 + CHUNK, N_EDGES);

    float acc[10];
#pragma unroll
    for (int q = 0; q < 10; q++) acc[q] = 0.f;

    // prefetch edge e0
    int      d_n = g_dstS[e0];
    unsigned pk  = g_srcrt[e0];
    int s_n = pk & 0xFFFFu, r_n = pk >> 16;
    float2 zs_n = *(const float2*)(g_z + s_n * F + 2 * lane);
    float ps_n[5], pd_n[5];
    {
        const float* pp = g_P + s_n * PCOLS + r_n * 5;
        const float* qq = g_P + d_n * PCOLS + 100 + r_n * 5;
#pragma unroll
        for (int h = 0; h < NHEADS; h++) { ps_n[h] = __ldg(pp + h); pd_n[h] = __ldg(qq + h); }
    }
    int d_cur = d_n;

    for (int i = e0; i < e1; i++) {
        const int    d_c = d_n;
        const float2 zs  = zs_n;
        float ps[5], pd[5];
#pragma unroll
        for (int h = 0; h < NHEADS; h++) { ps[h] = ps_n[h]; pd[h] = pd_n[h]; }

        if (i + 1 < e1) {
            d_n = g_dstS[i + 1];
            pk  = g_srcrt[i + 1];
            int s2 = pk & 0xFFFFu, r2 = pk >> 16;
            zs_n = *(const float2*)(g_z + s2 * F + 2 * lane);
            const float* pp = g_P + s2 * PCOLS + r2 * 5;
            const float* qq = g_P + d_n * PCOLS + 100 + r2 * 5;
#pragma unroll
            for (int h = 0; h < NHEADS; h++) { ps_n[h] = __ldg(pp + h); pd_n[h] = __ldg(qq + h); }
        }

        if (d_c != d_cur) {   // warp-uniform
            // ---- flush acc -> out[d_cur] ----
#pragma unroll
            for (int h = 0; h < NHEADS; h++)
                *(float2*)&stage[w][h * F + 2 * lane] = make_float2(acc[2 * h], acc[2 * h + 1]);
            __syncwarp();
            float* ob = out + (long)d_cur * OUTC;
#pragma unroll
            for (int t = 0; t < 3; t++) {
                int c = lane + 32 * t;
                if (c < 80) {
                    float4 v = *(const float4*)&stage[w][c * 4];
                    asm volatile("red.global.add.v4.f32 [%0], {%1, %2, %3, %4};"
                                 :: "l"(ob + 4 * c), "f"(v.x), "f"(v.y), "f"(v.z), "f"(v.w)
                                 : "memory");
                }
            }
            __syncwarp();
#pragma unroll
            for (int q = 0; q < 10; q++) acc[q] = 0.f;
            d_cur = d_c;
        }

#pragma unroll
        for (int h = 0; h < NHEADS; h++) {
            float a = ps[h] + pd[h];
            a = a > 0.f ? a : 0.01f * a;
            acc[2 * h]     += a * zs.x;
            acc[2 * h + 1] += a * zs.y;
        }
    }

    // final flush
#pragma unroll
    for (int h = 0; h < NHEADS; h++)
        *(float2*)&stage[w][h * F + 2 * lane] = make_float2(acc[2 * h], acc[2 * h + 1]);
    __syncwarp();
    float* ob = out + (long)d_cur * OUTC;
#pragma unroll
    for (int t = 0; t < 3; t++) {
        int c = lane + 32 * t;
        if (c < 80) {
            float4 v = *(const float4*)&stage[w][c * 4];
            asm volatile("red.global.add.v4.f32 [%0], {%1, %2, %3, %4};"
                         :: "l"(ob + 4 * c), "f"(v.x), "f"(v.y), "f"(v.z), "f"(v.w)
                         : "memory");
        }
    }
}

// ---------------------------------------------------------------------------
extern "C" void kernel_launch(void* const* d_in, const int* in_sizes, int n_in,
                              void* d_out, int out_size)
{
    const float* feat      = (const float*)d_in[0];
    const int*   src       = (const int*)  d_in[1];
    const int*   dst       = (const int*)  d_in[2];
    const int*   etype     = (const int*)  d_in[3];
    const float* fc_w      = (const float*)d_in[4];
    const float* self_fc_w = (const float*)d_in[5];
    const float* aw        = (const float*)d_in[6];
    const float* w_comp    = (const float*)d_in[7];
    float* out = (float*)d_out;

    const int NB = (N_NODES + 1023) / 1024;   // 25

    attn_zero_kernel<<<NRELS, 320>>>(aw, w_comp, fc_w);            // 1
    hist_kernel<<<(N_EDGES + 255) / 256, 256>>>(dst);              // 2
    scan1_kernel<<<NB, 1024>>>();                                  // 3
    scan3_kernel<<<NB, 1024>>>();                                  // 4
    scatter_kernel<<<(N_EDGES + 255) / 256, 256>>>(dst, src, etype); // 5
    proj_kernel<<<dim3((N_NODES + 127) / 128, 5), 256>>>(feat, fc_w, self_fc_w, out); // 6 (profiled)
    gather_kernel<<<(N_EDGES / CHUNK + 7) / 8, 256>>>(out);        // 7
}